// round 7
// baseline (speedup 1.0000x reference)
#include <cuda_runtime.h>
#include <math.h>

#define NPTS 262144
#define NLVL 16
#define TSZ  (1u << 19)
#define TMASK (TSZ - 1u)

typedef unsigned long long u64t;

__device__ __forceinline__ u64t pk2(float a, float b) {
    u64t r; asm("mov.b64 %0,{%1,%2};" : "=l"(r) : "f"(a), "f"(b)); return r;
}
__device__ __forceinline__ void upk2(u64t v, float& a, float& b) {
    asm("mov.b64 {%0,%1},%2;" : "=f"(a), "=f"(b) : "l"(v));
}
__device__ __forceinline__ void fma2(u64t& d, u64t a, u64t b) {
    asm("fma.rn.f32x2 %0,%1,%2,%0;" : "+l"(d) : "l"(a), "l"(b));
}

// ---------------------------------------------------------------------------
constexpr int OFF_SW0 = 0;            // 32*64
constexpr int OFF_SW1 = 2048;         // 64*64
constexpr int OFF_SW2 = 6144;         // 64*16
constexpr int OFF_CW0 = 7168;         // 42*64
constexpr int OFF_CW1 = 9856;         // 64*64
constexpr int OFF_CW2 = 13952;        // 64*3
constexpr int W_TOTAL = 14144;
__constant__ float c_w[W_TOTAL];

__constant__ int c_res[NLVL] = {16, 20, 25, 32, 40, 50, 64, 80,
                                101, 128, 161, 203, 256, 322, 406, 512};

constexpr int BP = 128;
constexpr int S  = 132;
constexpr int OFF_B0 = 0;
constexpr int OFF_B1 = 64 * S;
constexpr int SMEM_FLOATS = 2 * 64 * S;          // 16896
constexpr int SMEM_BYTES  = SMEM_FLOATS * 4;     // 67584

// ---------------------------------------------------------------------------
// GEMM: y[64][S] = act(W[IN][64]^T x[IN][S]).
// 8 warps x 8 neurons (4 natural cmem 64-bit pairs), lane -> 4 points.
// acc[point][neuron-pair]: weight pairs need NO duplication movs.
// ---------------------------------------------------------------------------
template <int IN, bool RELU>
__device__ __forceinline__ void gemmW(const float* __restrict__ xb,
                                      float* __restrict__ yb,
                                      int woff, int warp, int lane)
{
    u64t acc[4][4];
    #pragma unroll
    for (int q = 0; q < 4; q++)
        #pragma unroll
        for (int n = 0; n < 4; n++) acc[q][n] = 0ull;

    const float* xr = xb + lane * 4;
    const float* wr = c_w + woff + warp * 8;
    #pragma unroll 4
    for (int i = 0; i < IN; i++) {
        float4 xv = *(const float4*)(xr + i * S);
        u64t x0 = pk2(xv.x, xv.x);
        u64t x1 = pk2(xv.y, xv.y);
        u64t x2 = pk2(xv.z, xv.z);
        u64t x3 = pk2(xv.w, xv.w);
        #pragma unroll
        for (int n = 0; n < 4; n++) {
            u64t wp = *(const u64t*)(wr + i * 64 + 2 * n);   // natural pair
            fma2(acc[0][n], x0, wp);
            fma2(acc[1][n], x1, wp);
            fma2(acc[2][n], x2, wp);
            fma2(acc[3][n], x3, wp);
        }
    }
    #pragma unroll
    for (int n = 0; n < 4; n++) {
        float lo0, hi0, lo1, hi1, lo2, hi2, lo3, hi3;
        upk2(acc[0][n], lo0, hi0);
        upk2(acc[1][n], lo1, hi1);
        upk2(acc[2][n], lo2, hi2);
        upk2(acc[3][n], lo3, hi3);
        if (RELU) {
            lo0 = fmaxf(lo0, 0.f); lo1 = fmaxf(lo1, 0.f);
            lo2 = fmaxf(lo2, 0.f); lo3 = fmaxf(lo3, 0.f);
            hi0 = fmaxf(hi0, 0.f); hi1 = fmaxf(hi1, 0.f);
            hi2 = fmaxf(hi2, 0.f); hi3 = fmaxf(hi3, 0.f);
        }
        *(float4*)(yb + (warp * 8 + 2 * n + 0) * S + lane * 4) =
            make_float4(lo0, lo1, lo2, lo3);
        *(float4*)(yb + (warp * 8 + 2 * n + 1) * S + lane * 4) =
            make_float4(hi0, hi1, hi2, hi3);
    }
}

// sw2 (64 -> 16): 8 warps x 2 neurons (1 pair)
__device__ __forceinline__ void gemm16W(const float* __restrict__ xb,
                                        float* __restrict__ yb,
                                        int warp, int lane)
{
    u64t acc[4];
    #pragma unroll
    for (int q = 0; q < 4; q++) acc[q] = 0ull;

    const float* xr = xb + lane * 4;
    const float* wr = c_w + OFF_SW2 + warp * 2;
    #pragma unroll 8
    for (int i = 0; i < 64; i++) {
        float4 xv = *(const float4*)(xr + i * S);
        u64t wp = *(const u64t*)(wr + i * 16);
        fma2(acc[0], pk2(xv.x, xv.x), wp);
        fma2(acc[1], pk2(xv.y, xv.y), wp);
        fma2(acc[2], pk2(xv.z, xv.z), wp);
        fma2(acc[3], pk2(xv.w, xv.w), wp);
    }
    float lo0, hi0, lo1, hi1, lo2, hi2, lo3, hi3;
    upk2(acc[0], lo0, hi0);
    upk2(acc[1], lo1, hi1);
    upk2(acc[2], lo2, hi2);
    upk2(acc[3], lo3, hi3);
    *(float4*)(yb + (warp * 2 + 0) * S + lane * 4) =
        make_float4(lo0, lo1, lo2, lo3);
    *(float4*)(yb + (warp * 2 + 1) * S + lane * 4) =
        make_float4(hi0, hi1, hi2, hi3);
}

// ---------------------------------------------------------------------------
// Fused kernel: hash encode (-> smem) then MLPs. 128 points / block.
// ---------------------------------------------------------------------------
__global__ __launch_bounds__(256, 3) void fused_kernel(
    const float* __restrict__ xyzt,
    const float* __restrict__ dirs,
    const float* __restrict__ table,
    float* __restrict__ out)
{
    extern __shared__ float s[];
    const int tid = threadIdx.x;
    const int warp = tid >> 5, lane = tid & 31;
    const int gbase = blockIdx.x * BP;

    // ---- stage xyzt into B1 ----
    #pragma unroll
    for (int t = tid; t < 512; t += 256)
        s[OFF_B1 + t] = xyzt[(size_t)gbase * 4 + t];
    __syncthreads();

    // ---- hash phase: 2 threads per point, 8 levels each. Branchless. ----
    {
        const int p = tid & 127;
        const int lh = tid >> 7;                     // 0 or 1
        float4 pt = *(const float4*)(s + OFF_B1 + p * 4);

        #pragma unroll 2
        for (int k = 0; k < 8; k++) {
            const int l = 2 * k + lh;
            float r = (float)c_res[l];
            float px = pt.x * r, py = pt.y * r, pz = pt.z * r, pw = pt.w * r;
            float fx = floorf(px), fy = floorf(py), fz = floorf(pz), ft = floorf(pw);
            float wx = px - fx, wy = py - fy, wz = pz - fz, wt = pw - ft;
            unsigned cx = (unsigned)fx, cy = (unsigned)fy,
                     cz = (unsigned)fz, ct = (unsigned)ft;

            unsigned hx0 = cx,               hx1 = cx + 1u;
            unsigned hy0 = cy * 2654435761u, hy1 = (cy + 1u) * 2654435761u;
            unsigned hz0 = cz * 805459861u,  hz1 = (cz + 1u) * 805459861u;
            unsigned ht0 = ct * 3674653429u, ht1 = (ct + 1u) * 3674653429u;

            float wx0 = 1.f - wx, wy0 = 1.f - wy, wz0 = 1.f - wz, wt0 = 1.f - wt;

            const float2* tl = (const float2*)table + (size_t)l * TSZ;
            const float4* t4 = (const float4*)tl;
            const bool odd = (cx & 1u) != 0u;
            float a0 = 0.f, a1 = 0.f;

            #pragma unroll
            for (int c8 = 0; c8 < 8; c8++) {
                unsigned hyy = (c8 & 1) ? hy1 : hy0;
                unsigned hzz = (c8 & 2) ? hz1 : hz0;
                unsigned htt = (c8 & 4) ? ht1 : ht0;
                unsigned rest = hyy ^ hzz ^ htt;
                unsigned idx0 = (hx0 ^ rest) & TMASK;
                float wyzt = ((c8 & 1) ? wy : wy0) * ((c8 & 2) ? wz : wz0) *
                             ((c8 & 4) ? wt : wt0);
                float w0 = wx0 * wyzt, w1 = wx * wyzt;

                float4 v = __ldg(&t4[idx0 >> 1]);      // covers idx0 and idx0^1
                bool hi = (idx0 & 1u) != 0u;
                float f0x = hi ? v.z : v.x, f0y = hi ? v.w : v.y;
                float f1x = hi ? v.x : v.z, f1y = hi ? v.y : v.w;
                if (odd) {                              // predicated load
                    unsigned idx1 = (hx1 ^ rest) & TMASK;
                    float2 f1 = __ldg(&tl[idx1]);
                    f1x = f1.x; f1y = f1.y;
                }
                a0 = fmaf(f0x, w0, a0); a0 = fmaf(f1x, w1, a0);
                a1 = fmaf(f0y, w0, a1); a1 = fmaf(f1y, w1, a1);
            }
            s[OFF_B0 + (2 * l + 0) * S + p] = a0;
            s[OFF_B0 + (2 * l + 1) * S + p] = a1;
        }
    }
    __syncthreads();

    // ---- sigma net ----
    gemmW<32, true>(s + OFF_B0, s + OFF_B1, OFF_SW0, warp, lane);
    __syncthreads();
    gemmW<64, true>(s + OFF_B1, s + OFF_B0, OFF_SW1, warp, lane);
    __syncthreads();
    gemm16W(s + OFF_B0, s + OFF_B1, warp, lane);       // h -> B1 rows 0..15
    __syncthreads();

    // ---- color input assembly + sigma output ----
    if (tid < BP) {
        const int p = tid;
        const int gn = gbase + p;
        float d0 = dirs[(size_t)gn * 3 + 0];
        float d1 = dirs[(size_t)gn * 3 + 1];
        float d2 = dirs[(size_t)gn * 3 + 2];
        s[OFF_B0 + 0 * S + p] = d0;
        s[OFF_B0 + 1 * S + p] = d1;
        s[OFF_B0 + 2 * S + p] = d2;
        float dd[3] = {d0, d1, d2};
        #pragma unroll
        for (int f = 0; f < 4; f++) {
            float fr = (float)(1 << f);
            #pragma unroll
            for (int c = 0; c < 3; c++) {
                float ang = dd[c] * fr;
                s[OFF_B0 + (3 + f * 3 + c) * S + p]  = __sinf(ang);
                s[OFF_B0 + (15 + f * 3 + c) * S + p] = __cosf(ang);
            }
        }
        #pragma unroll
        for (int k = 0; k < 15; k++)
            s[OFF_B0 + (27 + k) * S + p] = s[OFF_B1 + (1 + k) * S + p];
        out[gn] = s[OFF_B1 + 0 * S + p];               // sigma
    }
    __syncthreads();

    // ---- color net ----
    gemmW<42, true>(s + OFF_B0, s + OFF_B1, OFF_CW0, warp, lane);
    __syncthreads();
    gemmW<64, true>(s + OFF_B1, s + OFF_B0, OFF_CW1, warp, lane);
    __syncthreads();

    // ---- final 64 -> 3 + sigmoid ----
    if (tid < BP) {
        const int p = tid;
        const int gn = gbase + p;
        float r0 = 0.f, r1 = 0.f, r2 = 0.f;
        #pragma unroll 8
        for (int i = 0; i < 64; i++) {
            float xv = s[OFF_B0 + i * S + p];
            r0 = fmaf(xv, c_w[OFF_CW2 + i * 3 + 0], r0);
            r1 = fmaf(xv, c_w[OFF_CW2 + i * 3 + 1], r1);
            r2 = fmaf(xv, c_w[OFF_CW2 + i * 3 + 2], r2);
        }
        out[(size_t)NPTS + (size_t)gn * 3 + 0] = 1.f / (1.f + __expf(-r0));
        out[(size_t)NPTS + (size_t)gn * 3 + 1] = 1.f / (1.f + __expf(-r1));
        out[(size_t)NPTS + (size_t)gn * 3 + 2] = 1.f / (1.f + __expf(-r2));
    }
}

// ---------------------------------------------------------------------------
extern "C" void kernel_launch(void* const* d_in, const int* in_sizes, int n_in,
                              void* d_out, int out_size)
{
    const float* xyzt  = (const float*)d_in[0];
    const float* dirs  = (const float*)d_in[1];
    const float* table = (const float*)d_in[2];

    cudaMemcpyToSymbolAsync(c_w, d_in[3], 2048 * 4, OFF_SW0 * 4,
                            cudaMemcpyDeviceToDevice);
    cudaMemcpyToSymbolAsync(c_w, d_in[4], 4096 * 4, OFF_SW1 * 4,
                            cudaMemcpyDeviceToDevice);
    cudaMemcpyToSymbolAsync(c_w, d_in[5], 1024 * 4, OFF_SW2 * 4,
                            cudaMemcpyDeviceToDevice);
    cudaMemcpyToSymbolAsync(c_w, d_in[6], 2688 * 4, OFF_CW0 * 4,
                            cudaMemcpyDeviceToDevice);
    cudaMemcpyToSymbolAsync(c_w, d_in[7], 4096 * 4, OFF_CW1 * 4,
                            cudaMemcpyDeviceToDevice);
    cudaMemcpyToSymbolAsync(c_w, d_in[8], 192 * 4, OFF_CW2 * 4,
                            cudaMemcpyDeviceToDevice);

    cudaFuncSetAttribute(fused_kernel, cudaFuncAttributeMaxDynamicSharedMemorySize,
                         SMEM_BYTES);

    fused_kernel<<<NPTS / BP, 256, SMEM_BYTES>>>(xyzt, dirs, table, (float*)d_out);
}